// round 3
// baseline (speedup 1.0000x reference)
#include <cuda_runtime.h>
#include <cstddef>

#define NEG (-1e20f)

constexpr int NA = 512;    // rows i = 1..NA
constexpr int NB = 1024;   // cols j = 1..NB
constexpr int NT = 1024;   // threads = one per column
constexpr int NWIN = 48;   // 48 windows * 32 steps = steps s in [2, 1537]

// shared memory layout:
//   wband   [32][1024] f32 : W values for current 32-step window (slot = s&31)
//   outband [512][32]  f32 : computed mu awaiting coalesced flush
//   ring    [32][64]   u64 : per producer-warp boundary stream {tag=s, value}
constexpr int WBAND_F   = 32 * NB;      // 32768 floats
constexpr int OUTBAND_F = NA * 32;      // 16384 floats
constexpr int RING_D    = 64;
constexpr int RING_U64  = 32 * RING_D;  // 2048 u64 = 16KB
constexpr size_t SMEM_BYTES = (size_t)(WBAND_F + OUTBAND_F) * 4 + RING_U64 * 8;

__device__ __forceinline__ float lse3(float a, float b, float c) {
    float m = fmaxf(a, fmaxf(b, c));
    float s = __expf(a - m) + __expf(b - m) + __expf(c - m);
    return m + __logf(s);
}

__device__ __forceinline__ unsigned long long pack_sv(int s, float v) {
    return ((unsigned long long)(unsigned)s << 32) | (unsigned long long)__float_as_uint(v);
}

__global__ void __launch_bounds__(NT, 1)
dtw_wavefront_kernel(const float* __restrict__ W, float* __restrict__ out) {
    extern __shared__ float smem[];
    float* wband   = smem;                    // [slot][t]
    float* outband = smem + WBAND_F;          // [r][(j-1)&31]
    volatile unsigned long long* ring =
        (volatile unsigned long long*)(smem + WBAND_F + OUTBAND_F); // [warp][slot]

    const int b    = blockIdx.x;
    const int t    = threadIdx.x;             // column j = t + 1
    const int lane = t & 31;
    const int wid  = t >> 5;
    const int c0   = wid << 5;                // stripe base column index

    const float* Wb = W + (size_t)b * NA * NB;
    float* Ob = out + (size_t)b * (NA + 1) * (NB + 1);

    // --- edge outputs: mu[0, :] and mu[:, 0] ---
    Ob[t] = (t == 0) ? 0.0f : NEG;                        // row 0, cols 0..1023
    if (t == 0) Ob[NB] = NEG;                             // row 0, col 1024
    if (t < NA)  Ob[(size_t)(t + 1) * (NB + 1)] = NEG;    // col 0

    // init ring tags to -1 (invalid)
    ring[t]        = pack_sv(-1, NEG);
    ring[t + 1024] = pack_sv(-1, NEG);
    __syncthreads();

    float v1    = NEG;   // this column's latest mu (starts as mu[0, j] = NEG)
    float lprev = NEG;   // left neighbor's v1 from previous step (upper-left)

    // warp activity range: steps s in [c0+2, c0+544]
    const int s_first = c0 + 2;
    const int s_last  = c0 + 32 + NA;         // c0 + 544

    for (int k = 0; k < NWIN; ++k) {
        const int S = 2 + 32 * k;

        // ---- cooperative wband fill for steps [S, S+32): coalesced rows ----
        {
            float vals[16];
            int   tts[16];
            #pragma unroll
            for (int m = 0; m < 16; ++m) {
                int r  = wid + (m << 5);
                int tt = S - 2 - r + lane;
                bool ok = (tt >= 0) && (tt < NB);
                tts[m] = ok ? tt : -1;
                vals[m] = ok ? Wb[r * NB + tt] : 0.0f;
            }
            const int slot = (lane + 2) & 31;
            #pragma unroll
            for (int m = 0; m < 16; ++m) {
                if (tts[m] >= 0) wband[slot * NB + tts[m]] = vals[m];
            }
        }
        __syncthreads();

        // ---- 32 wavefront steps, warp-autonomous (no block barrier) ----
        if (S + 31 >= s_first && S <= s_last) {
            #pragma unroll 4
            for (int q = 0; q < 32; ++q) {
                const int s = S + q;
                const int i = s - t - 1;          // row computed by this lane
                const bool act = (i >= 1) && (i <= NA);

                float lv = __shfl_up_sync(0xFFFFFFFFu, v1, 1);
                if (lane == 0) {
                    if (wid > 0 && act) {
                        // spin for producer warp's step s-1 boundary value
                        unsigned long long p;
                        do {
                            p = ring[(wid - 1) * RING_D + ((s - 1) & (RING_D - 1))];
                        } while ((int)(p >> 32) != s - 1);
                        lv = __uint_as_float((unsigned)p);
                    } else {
                        lv = NEG;
                    }
                }
                float ul = lprev;
                if (t == 0) { lv = NEG; ul = (i == 1) ? 0.0f : NEG; }

                if (act) {
                    float w    = wband[(s & 31) * NB + t];
                    float mval = lse3(v1, lv, ul) + w;
                    outband[(i - 1) * 32 + (t & 31)] = mval;
                    v1 = mval;
                    if (lane == 31) {
                        ring[wid * RING_D + (s & (RING_D - 1))] = pack_sv(s, mval);
                    }
                }
                lprev = lv;
            }
        }
        __syncthreads();

        // ---- flush outband: cells computed in steps [S, S+32) ----
        #pragma unroll
        for (int m = 0; m < 16; ++m) {
            int r = wid + (m << 5);
            int i = r + 1;
            int j = S - i + lane;
            if (j >= 1 && j <= NB) {
                Ob[(size_t)i * (NB + 1) + j] = outband[r * 32 + ((j - 1) & 31)];
            }
        }
        __syncthreads();
    }
}

extern "C" void kernel_launch(void* const* d_in, const int* in_sizes, int n_in,
                              void* d_out, int out_size) {
    const float* W = (const float*)d_in[0];
    float* out = (float*)d_out;
    cudaFuncSetAttribute(dtw_wavefront_kernel,
                         cudaFuncAttributeMaxDynamicSharedMemorySize,
                         (int)SMEM_BYTES);
    dtw_wavefront_kernel<<<32, NT, SMEM_BYTES>>>(W, out);
}